// round 7
// baseline (speedup 1.0000x reference)
#include <cuda_runtime.h>
#include <cuda_bf16.h>
#include <cstdint>

#define NB   1024
#define NS1  25
#define NS2  10
#define DF   128
#define ROWS1 (NB * NS1)   // 25600

// ---------------- scratch (no allocations allowed) ----------------
__device__ float g_Y1[(size_t)ROWS1 * 256];
__device__ float g_X0[(size_t)NB * 256];
__device__ float g_Y0[(size_t)NB * 256];
__device__ float g_M1[(size_t)NB * 256];
__device__ __align__(16) __nv_bfloat16 g_WtH[2 * 128 * 128];  // W^T hi, [half][n][k]
__device__ __align__(16) __nv_bfloat16 g_WtL[2 * 128 * 128];  // W^T lo

// ---------------- helpers ----------------
__device__ __forceinline__ void split4(const float4& v, uint2& hi, uint2& lo) {
    float vv[4] = {v.x, v.y, v.z, v.w};
    uint32_t hp[2], lp[2];
#pragma unroll
    for (int q = 0; q < 2; q++) {
        __nv_bfloat16 h0 = __float2bfloat16(vv[2 * q]);
        __nv_bfloat16 h1 = __float2bfloat16(vv[2 * q + 1]);
        __nv_bfloat16 l0 = __float2bfloat16(vv[2 * q] - __bfloat162float(h0));
        __nv_bfloat16 l1 = __float2bfloat16(vv[2 * q + 1] - __bfloat162float(h1));
        hp[q] = ((uint32_t)__bfloat16_as_ushort(h1) << 16) | __bfloat16_as_ushort(h0);
        lp[q] = ((uint32_t)__bfloat16_as_ushort(l1) << 16) | __bfloat16_as_ushort(l0);
    }
    hi = make_uint2(hp[0], hp[1]);
    lo = make_uint2(lp[0], lp[1]);
}
__device__ __forceinline__ uint32_t smem_to_u32(const void* p) {
    uint32_t a;
    asm("{ .reg .u64 t; cvta.to.shared.u64 t, %1; cvt.u32.u64 %0, t; }"
        : "=r"(a) : "l"(p));
    return a;
}
#define CP_ASYNC16(dst_u32, src_ptr) \
    asm volatile("cp.async.cg.shared.global [%0], [%1], 16;" \
        :: "r"(dst_u32), "l"(src_ptr) : "memory")
#define CP_ASYNC_WAIT_ALL() \
    asm volatile("cp.async.commit_group;\ncp.async.wait_group 0;" ::: "memory")

__device__ __forceinline__ void mma16816(float* c, const uint32_t* a, const uint32_t* b) {
    asm volatile(
        "mma.sync.aligned.m16n8k16.row.col.f32.bf16.bf16.f32 "
        "{%0,%1,%2,%3}, {%4,%5,%6,%7}, {%8,%9}, {%0,%1,%2,%3};"
        : "+f"(c[0]), "+f"(c[1]), "+f"(c[2]), "+f"(c[3])
        : "r"(a[0]), "r"(a[1]), "r"(a[2]), "r"(a[3]), "r"(b[0]), "r"(b[1]));
}

// ---------------- prep: transpose + bf16-split the layer-0 weights ----------------
__global__ void prep_w_kernel(const float* __restrict__ w0,
                              const float* __restrict__ w1) {
    __shared__ float t[32][33];
    int b = blockIdx.x;
    int half = b >> 4;
    int tile = b & 15;
    int tr = (tile >> 2) * 32;   // k base
    int tc = (tile & 3) * 32;    // n base
    const float* W = half ? w1 : w0;
    int tx = threadIdx.x & 31, ty = threadIdx.x >> 5;   // 32x8
#pragma unroll
    for (int p = 0; p < 32; p += 8)
        t[ty + p][tx] = W[(size_t)(tr + ty + p) * 128 + tc + tx];
    __syncthreads();
#pragma unroll
    for (int p = 0; p < 32; p += 8) {
        int n = tc + ty + p, k = tr + tx;
        float v = t[tx][ty + p];
        __nv_bfloat16 h = __float2bfloat16(v);
        __nv_bfloat16 l = __float2bfloat16(v - __bfloat162float(h));
        size_t o = ((size_t)half * 128 + n) * 128 + k;
        g_WtH[o] = h;
        g_WtL[o] = l;
    }
}

// ---------------- gather0: X0 = [h0 | mean_S1(h1)] straight from features ----------------
__global__ void gather0_kernel(const float* __restrict__ feat,
                               const int* __restrict__ s0,
                               const int* __restrict__ s1) {
    int warp = (blockIdx.x * blockDim.x + threadIdx.x) >> 5;
    int lane = threadIdx.x & 31;
    if (warp >= NB) return;
    int c = lane * 4;

    long iself = s0[warp];
    *(float4*)(g_X0 + (size_t)warp * 256 + c) =
        *(const float4*)(feat + iself * DF + c);

    const int* p = s1 + (size_t)warp * NS1;
    float4 acc = make_float4(0.f, 0.f, 0.f, 0.f);
#pragma unroll 5
    for (int j = 0; j < NS1; j++) {
        float4 v = *(const float4*)(feat + (long)p[j] * DF + c);
        acc.x += v.x; acc.y += v.y; acc.z += v.z; acc.w += v.w;
    }
    const float s = 1.0f / NS1;
    acc.x *= s; acc.y *= s; acc.z *= s; acc.w *= s;
    *(float4*)(g_X0 + (size_t)warp * 256 + 128 + c) = acc;
}

// ---------------- fused gather + GEMM (HMMA bf16x3) ----------------
// grid (400, 2): 64 rows x 128 cols per CTA; half = blockIdx.y.
// Staging: warp w gathers rows {w, w+8, ..., w+56} straight from features:
//   half=0: A row = feat[s1[row]]            (self)
//   half=1: A row = mean_j feat[s2[row][j]]  (neighbor mean)
// split to bf16 hi/lo, STS. B = prepped W^T hi/lo via cp.async. Then MMA.
#define PADB 272   // smem row pitch in bytes

__global__ __launch_bounds__(256)
void gemm_fused_kernel(const float* __restrict__ feat,
                       const int* __restrict__ s1,
                       const int* __restrict__ s2) {
    extern __shared__ char sb[];
    const uint32_t OFF_AH = 0;
    const uint32_t OFF_AL = 64 * PADB;
    const uint32_t OFF_BH = 2 * 64 * PADB;
    const uint32_t OFF_BL = OFF_BH + 128 * PADB;
    const uint32_t smb = smem_to_u32(sb);

    const int half = blockIdx.y;
    const int row0 = blockIdx.x * 64;
    const int tid = threadIdx.x;
    const int wid = tid >> 5;
    const int lane = tid & 31;

    // ---- stage B first (async, overlaps the A gather) ----
    for (int idx = tid; idx < 2048; idx += 256) {
        int n = idx >> 4;
        int ch = (idx & 15) * 16;
        size_t gsrc = (size_t)half * 16384 + (size_t)n * 128;
        uint32_t dst = n * PADB + ch;
        CP_ASYNC16(smb + OFF_BH + dst, (const char*)(g_WtH + gsrc) + ch);
        CP_ASYNC16(smb + OFF_BL + dst, (const char*)(g_WtL + gsrc) + ch);
    }

    // ---- gather A: 8 rows per warp ----
    const int c = lane * 4;
#pragma unroll
    for (int it = 0; it < 8; it++) {
        const int r = wid + it * 8;
        const int gr = row0 + r;
        float4 val;
        if (half == 0) {
            long idx = s1[gr];
            val = *(const float4*)(feat + idx * DF + c);
        } else {
            const int* p = s2 + (size_t)gr * NS2;
            int idxs[NS2];
#pragma unroll
            for (int j = 0; j < NS2; j++) idxs[j] = p[j];
            float4 acc = make_float4(0.f, 0.f, 0.f, 0.f);
#pragma unroll
            for (int j = 0; j < NS2; j++) {
                float4 v = *(const float4*)(feat + (long)idxs[j] * DF + c);
                acc.x += v.x; acc.y += v.y; acc.z += v.z; acc.w += v.w;
            }
            const float s = 1.0f / NS2;
            acc.x *= s; acc.y *= s; acc.z *= s; acc.w *= s;
            val = acc;
        }
        uint2 h, l;
        split4(val, h, l);
        *(uint2*)(sb + OFF_AH + r * PADB + lane * 8) = h;
        *(uint2*)(sb + OFF_AL + r * PADB + lane * 8) = l;
    }
    CP_ASYNC_WAIT_ALL();
    __syncthreads();

    const char* Ah = sb + OFF_AH;
    const char* Al = sb + OFF_AL;
    const char* Bh = sb + OFF_BH;
    const char* Bl = sb + OFF_BL;

    const int g = lane >> 2;
    const int tg = lane & 3;
    const int wr = (wid >> 2) * 32;   // warp row base
    const int wc = (wid & 3) * 32;    // warp col base

    float acc[2][4][4];
#pragma unroll
    for (int i = 0; i < 2; i++)
#pragma unroll
        for (int j = 0; j < 4; j++)
#pragma unroll
            for (int q = 0; q < 4; q++) acc[i][j][q] = 0.f;

#pragma unroll
    for (int ks = 0; ks < 8; ks++) {
        const int kb = (ks * 16 + tg * 2) * 2;
        uint32_t ah[2][4], al[2][4], bh[4][2], bl[4][2];
#pragma unroll
        for (int i = 0; i < 2; i++) {
            int r = wr + i * 16 + g;
            ah[i][0] = *(const uint32_t*)(Ah + r * PADB + kb);
            ah[i][1] = *(const uint32_t*)(Ah + (r + 8) * PADB + kb);
            ah[i][2] = *(const uint32_t*)(Ah + r * PADB + kb + 16);
            ah[i][3] = *(const uint32_t*)(Ah + (r + 8) * PADB + kb + 16);
            al[i][0] = *(const uint32_t*)(Al + r * PADB + kb);
            al[i][1] = *(const uint32_t*)(Al + (r + 8) * PADB + kb);
            al[i][2] = *(const uint32_t*)(Al + r * PADB + kb + 16);
            al[i][3] = *(const uint32_t*)(Al + (r + 8) * PADB + kb + 16);
        }
#pragma unroll
        for (int j = 0; j < 4; j++) {
            int n = wc + j * 8 + g;
            bh[j][0] = *(const uint32_t*)(Bh + n * PADB + kb);
            bh[j][1] = *(const uint32_t*)(Bh + n * PADB + kb + 16);
            bl[j][0] = *(const uint32_t*)(Bl + n * PADB + kb);
            bl[j][1] = *(const uint32_t*)(Bl + n * PADB + kb + 16);
        }
#pragma unroll
        for (int i = 0; i < 2; i++)
#pragma unroll
            for (int j = 0; j < 4; j++) {
                mma16816(acc[i][j], ah[i], bh[j]);
                mma16816(acc[i][j], al[i], bh[j]);
                mma16816(acc[i][j], ah[i], bl[j]);
            }
    }

    // ---- epilogue: relu + STG.64 into Y1 ----
    const int colg = half * 128 + wc;
#pragma unroll
    for (int i = 0; i < 2; i++) {
        int r = row0 + wr + i * 16 + g;
#pragma unroll
        for (int j = 0; j < 4; j++) {
            int cgl = colg + j * 8 + tg * 2;
            float2 o0, o1;
            o0.x = fmaxf(acc[i][j][0], 0.f);
            o0.y = fmaxf(acc[i][j][1], 0.f);
            o1.x = fmaxf(acc[i][j][2], 0.f);
            o1.y = fmaxf(acc[i][j][3], 0.f);
            *(float2*)(g_Y1 + (size_t)r * 256 + cgl) = o0;
            *(float2*)(g_Y1 + (size_t)(r + 8) * 256 + cgl) = o1;
        }
    }
}

// ---------------- small GEMM + ReLU (tiled, W in smem) ----------------
template <int K>
__global__ __launch_bounds__(256)
void gemm_small_kernel(const float* __restrict__ A0, const float* __restrict__ W0,
                       const float* __restrict__ A1, const float* __restrict__ W1,
                       float* __restrict__ out) {
    extern __shared__ float sm[];
    float* As = sm;             // [K][32] transposed
    float* Bs = sm + K * 32;    // [K][64]

    const int half = blockIdx.y >> 1;
    const float* A = half ? A1 : A0;
    const float* W = half ? W1 : W0;
    const int wcol0 = (blockIdx.y & 1) * 64;
    const int row0 = blockIdx.x * 32;
    const int tid = threadIdx.x;

    for (int idx = tid; idx < 32 * (K / 4); idx += 256) {
        int r  = idx & 31;
        int k4 = (idx >> 5) * 4;
        float4 v = *(const float4*)(A + (size_t)(row0 + r) * 256 + k4);
        As[(k4 + 0) * 32 + r] = v.x;
        As[(k4 + 1) * 32 + r] = v.y;
        As[(k4 + 2) * 32 + r] = v.z;
        As[(k4 + 3) * 32 + r] = v.w;
    }
    for (int idx = tid; idx < K * 16; idx += 256) {
        int k = idx >> 4;
        int j4 = (idx & 15) * 4;
        *(float4*)(Bs + k * 64 + j4) =
            *(const float4*)(W + (size_t)k * 128 + wcol0 + j4);
    }
    __syncthreads();

    const int rr = (tid & 15) * 2;
    const int cc = (tid >> 4) * 4;

    float acc[2][4];
#pragma unroll
    for (int i = 0; i < 2; i++)
#pragma unroll
        for (int j = 0; j < 4; j++) acc[i][j] = 0.f;

#pragma unroll 8
    for (int k = 0; k < K; k++) {
        float2 a = *(const float2*)(As + k * 32 + rr);
        float4 b = *(const float4*)(Bs + k * 64 + cc);
        acc[0][0] = fmaf(a.x, b.x, acc[0][0]);
        acc[0][1] = fmaf(a.x, b.y, acc[0][1]);
        acc[0][2] = fmaf(a.x, b.z, acc[0][2]);
        acc[0][3] = fmaf(a.x, b.w, acc[0][3]);
        acc[1][0] = fmaf(a.y, b.x, acc[1][0]);
        acc[1][1] = fmaf(a.y, b.y, acc[1][1]);
        acc[1][2] = fmaf(a.y, b.z, acc[1][2]);
        acc[1][3] = fmaf(a.y, b.w, acc[1][3]);
    }

    const int ncol = blockIdx.y * 64 + cc;
#pragma unroll
    for (int i = 0; i < 2; i++) {
        float4 o;
        o.x = fmaxf(acc[i][0], 0.f); o.y = fmaxf(acc[i][1], 0.f);
        o.z = fmaxf(acc[i][2], 0.f); o.w = fmaxf(acc[i][3], 0.f);
        *(float4*)(out + (size_t)(row0 + rr + i) * 256 + ncol) = o;
    }
}

// ---------------- mean over S1 of Y1 -> M1 ----------------
__global__ void mean25_kernel() {
    int t = blockIdx.x * blockDim.x + threadIdx.x;
    if (t >= NB * 64) return;
    int b = t >> 6;
    int q = t & 63;
    const float4* base = (const float4*)g_Y1 + (size_t)b * NS1 * 64 + q;
    float4 acc = make_float4(0.f, 0.f, 0.f, 0.f);
#pragma unroll
    for (int j = 0; j < NS1; j++) {
        float4 v = base[(size_t)j * 64];
        acc.x += v.x; acc.y += v.y; acc.z += v.z; acc.w += v.w;
    }
    const float s = 1.0f / NS1;
    acc.x *= s; acc.y *= s; acc.z *= s; acc.w *= s;
    ((float4*)g_M1)[(size_t)b * 64 + q] = acc;
}

// ---------------- launch ----------------
extern "C" void kernel_launch(void* const* d_in, const int* in_sizes, int n_in,
                              void* d_out, int out_size) {
    const float* feat = (const float*)d_in[0];
    const float* ws0  = (const float*)d_in[1];
    const float* wn0  = (const float*)d_in[2];
    const float* ws1  = (const float*)d_in[3];
    const float* wn1  = (const float*)d_in[4];
    const int*   s0   = (const int*)d_in[5];
    const int*   s1   = (const int*)d_in[6];
    const int*   s2   = (const int*)d_in[7];
    float* out = (float*)d_out;

    float *pX0, *pY0, *pM1;
    cudaGetSymbolAddress((void**)&pX0, g_X0);
    cudaGetSymbolAddress((void**)&pY0, g_Y0);
    cudaGetSymbolAddress((void**)&pM1, g_M1);

    const size_t smMMA  = (size_t)(2 * 64 + 2 * 128) * PADB;               // 104448
    const size_t smS128 = (size_t)(128 * 32 + 128 * 64) * sizeof(float);   //  48 KB
    const size_t smS256 = (size_t)(256 * 32 + 256 * 64) * sizeof(float);   //  96 KB
    cudaFuncSetAttribute(gemm_fused_kernel,
                         cudaFuncAttributeMaxDynamicSharedMemorySize, (int)smMMA);
    cudaFuncSetAttribute(gemm_small_kernel<128>,
                         cudaFuncAttributeMaxDynamicSharedMemorySize, (int)smS128);
    cudaFuncSetAttribute(gemm_small_kernel<256>,
                         cudaFuncAttributeMaxDynamicSharedMemorySize, (int)smS256);

    // 1) prep W0/W1 -> transposed bf16 hi/lo
    prep_w_kernel<<<32, 256>>>(ws0, wn0);
    // 2) X0 = [h0 | mean_S1(h1)] (direct from features)
    gather0_kernel<<<(NB * 32 + 255) / 256, 256>>>(feat, s0, s1);
    // 3) Y0 = relu([X0s@Ws0 | X0n@Wn0])
    gemm_small_kernel<128><<<dim3(NB / 32, 4), 256, smS128>>>(pX0, ws0, pX0 + 128, wn0, pY0);
    // 4) Y1 = relu([gather(X1)s@Ws0 | gather(X1)n@Wn0]) — fused, profiled position
    gemm_fused_kernel<<<dim3(ROWS1 / 64, 2), 256, smMMA>>>(feat, s1, s2);
    // 5) M1 = mean_S1(Y1)
    mean25_kernel<<<(NB * 64 + 255) / 256, 256>>>();
    // 6) out = relu([Y0@Ws1 | M1@Wn1])
    gemm_small_kernel<256><<<dim3(NB / 32, 4), 256, smS256>>>(pY0, ws1, pM1, wn1, out);
}

// round 8
// speedup vs baseline: 1.0589x; 1.0589x over previous
#include <cuda_runtime.h>
#include <cuda_bf16.h>
#include <cstdint>

#define NB   1024
#define NS1  25
#define NS2  10
#define DF   128
#define ROWS1 (NB * NS1)   // 25600

// ---------------- scratch (no allocations allowed) ----------------
__device__ float g_Y1[(size_t)ROWS1 * 256];
__device__ float g_X0[(size_t)NB * 256];
__device__ float g_Y0[(size_t)NB * 256];
__device__ float g_M1[(size_t)NB * 256];
__device__ __align__(16) __nv_bfloat16 g_WtH[2 * 128 * 128];  // W^T hi, [half][n][k]
__device__ __align__(16) __nv_bfloat16 g_WtL[2 * 128 * 128];  // W^T lo

// ---------------- helpers ----------------
__device__ __forceinline__ void split4(const float4& v, uint2& hi, uint2& lo) {
    float vv[4] = {v.x, v.y, v.z, v.w};
    uint32_t hp[2], lp[2];
#pragma unroll
    for (int q = 0; q < 2; q++) {
        __nv_bfloat16 h0 = __float2bfloat16(vv[2 * q]);
        __nv_bfloat16 h1 = __float2bfloat16(vv[2 * q + 1]);
        __nv_bfloat16 l0 = __float2bfloat16(vv[2 * q] - __bfloat162float(h0));
        __nv_bfloat16 l1 = __float2bfloat16(vv[2 * q + 1] - __bfloat162float(h1));
        hp[q] = ((uint32_t)__bfloat16_as_ushort(h1) << 16) | __bfloat16_as_ushort(h0);
        lp[q] = ((uint32_t)__bfloat16_as_ushort(l1) << 16) | __bfloat16_as_ushort(l0);
    }
    hi = make_uint2(hp[0], hp[1]);
    lo = make_uint2(lp[0], lp[1]);
}
__device__ __forceinline__ uint32_t smem_to_u32(const void* p) {
    uint32_t a;
    asm("{ .reg .u64 t; cvta.to.shared.u64 t, %1; cvt.u32.u64 %0, t; }"
        : "=r"(a) : "l"(p));
    return a;
}
#define CP_ASYNC16(dst_u32, src_ptr) \
    asm volatile("cp.async.cg.shared.global [%0], [%1], 16;" \
        :: "r"(dst_u32), "l"(src_ptr) : "memory")
#define CP_ASYNC_WAIT_ALL() \
    asm volatile("cp.async.commit_group;\ncp.async.wait_group 0;" ::: "memory")

__device__ __forceinline__ void mma16816(float* c, const uint32_t* a, const uint32_t* b) {
    asm volatile(
        "mma.sync.aligned.m16n8k16.row.col.f32.bf16.bf16.f32 "
        "{%0,%1,%2,%3}, {%4,%5,%6,%7}, {%8,%9}, {%0,%1,%2,%3};"
        : "+f"(c[0]), "+f"(c[1]), "+f"(c[2]), "+f"(c[3])
        : "r"(a[0]), "r"(a[1]), "r"(a[2]), "r"(a[3]), "r"(b[0]), "r"(b[1]));
}
__device__ __forceinline__ void f4add(float4& a, const float4& b) {
    a.x += b.x; a.y += b.y; a.z += b.z; a.w += b.w;
}

// ---------------- prep: transpose + bf16-split the layer-0 weights ----------------
__global__ void prep_w_kernel(const float* __restrict__ w0,
                              const float* __restrict__ w1) {
    __shared__ float t[32][33];
    int b = blockIdx.x;
    int half = b >> 4;
    int tile = b & 15;
    int tr = (tile >> 2) * 32;   // k base
    int tc = (tile & 3) * 32;    // n base
    const float* W = half ? w1 : w0;
    int tx = threadIdx.x & 31, ty = threadIdx.x >> 5;   // 32x8
#pragma unroll
    for (int p = 0; p < 32; p += 8)
        t[ty + p][tx] = W[(size_t)(tr + ty + p) * 128 + tc + tx];
    __syncthreads();
#pragma unroll
    for (int p = 0; p < 32; p += 8) {
        int n = tc + ty + p, k = tr + tx;
        float v = t[tx][ty + p];
        __nv_bfloat16 h = __float2bfloat16(v);
        __nv_bfloat16 l = __float2bfloat16(v - __bfloat162float(h));
        size_t o = ((size_t)half * 128 + n) * 128 + k;
        g_WtH[o] = h;
        g_WtL[o] = l;
    }
}

// ---------------- gather0: X0 = [h0 | mean_S1(h1)], MLP-batched ----------------
__global__ void gather0_kernel(const float* __restrict__ feat,
                               const int* __restrict__ s0,
                               const int* __restrict__ s1) {
    int warp = (blockIdx.x * blockDim.x + threadIdx.x) >> 5;
    int lane = threadIdx.x & 31;
    if (warp >= NB) return;
    int c = lane * 4;

    long iself = s0[warp];
    *(float4*)(g_X0 + (size_t)warp * 256 + c) =
        *(const float4*)(feat + iself * DF + c);

    const int* p = s1 + (size_t)warp * NS1;
    int idxs[NS1];
#pragma unroll
    for (int j = 0; j < NS1; j++) idxs[j] = p[j];

    float4 acc = make_float4(0.f, 0.f, 0.f, 0.f);
#pragma unroll
    for (int base = 0; base < 25; base += 5) {
        float4 v[5];
#pragma unroll
        for (int j = 0; j < 5; j++)
            v[j] = *(const float4*)(feat + (long)idxs[base + j] * DF + c);
        f4add(v[0], v[1]); f4add(v[2], v[3]); f4add(v[0], v[2]);
        f4add(v[0], v[4]); f4add(acc, v[0]);
    }
    const float s = 1.0f / NS1;
    acc.x *= s; acc.y *= s; acc.z *= s; acc.w *= s;
    *(float4*)(g_X0 + (size_t)warp * 256 + 128 + c) = acc;
}

// ---------------- fused gather + GEMM (HMMA bf16x3), MLP-batched gather ----------------
#define PADB 272   // smem row pitch in bytes

__global__ __launch_bounds__(256, 2)
void gemm_fused_kernel(const float* __restrict__ feat,
                       const int* __restrict__ s1,
                       const int* __restrict__ s2) {
    extern __shared__ char sb[];
    const uint32_t OFF_AH = 0;
    const uint32_t OFF_AL = 64 * PADB;
    const uint32_t OFF_BH = 2 * 64 * PADB;
    const uint32_t OFF_BL = OFF_BH + 128 * PADB;
    const uint32_t smb = smem_to_u32(sb);

    const int half = blockIdx.y;
    const int row0 = blockIdx.x * 64;
    const int tid = threadIdx.x;
    const int wid = tid >> 5;
    const int lane = tid & 31;

    // ---- stage B first (async, overlaps the A gather) ----
    for (int idx = tid; idx < 2048; idx += 256) {
        int n = idx >> 4;
        int ch = (idx & 15) * 16;
        size_t gsrc = (size_t)half * 16384 + (size_t)n * 128;
        uint32_t dst = n * PADB + ch;
        CP_ASYNC16(smb + OFF_BH + dst, (const char*)(g_WtH + gsrc) + ch);
        CP_ASYNC16(smb + OFF_BL + dst, (const char*)(g_WtL + gsrc) + ch);
    }

    // ---- gather A: 8 rows per warp, loads explicitly batched for MLP ----
    const int c = lane * 4;
    if (half == 0) {
        long idxs[8];
#pragma unroll
        for (int it = 0; it < 8; it++) idxs[it] = s1[row0 + wid + it * 8];
        float4 v[8];
#pragma unroll
        for (int it = 0; it < 8; it++)
            v[it] = *(const float4*)(feat + idxs[it] * DF + c);
#pragma unroll
        for (int it = 0; it < 8; it++) {
            const int r = wid + it * 8;
            uint2 h, l;
            split4(v[it], h, l);
            *(uint2*)(sb + OFF_AH + r * PADB + lane * 8) = h;
            *(uint2*)(sb + OFF_AL + r * PADB + lane * 8) = l;
        }
    } else {
#pragma unroll
        for (int it = 0; it < 8; it++) {
            const int r = wid + it * 8;
            const int gr = row0 + r;
            const int* p = s2 + (size_t)gr * NS2;
            int idxs[NS2];
#pragma unroll
            for (int j = 0; j < NS2; j++) idxs[j] = p[j];
            float4 v[NS2];
#pragma unroll
            for (int j = 0; j < NS2; j++)
                v[j] = *(const float4*)(feat + (long)idxs[j] * DF + c);
            // pairwise tree sum (short dep chain)
            f4add(v[0], v[1]); f4add(v[2], v[3]); f4add(v[4], v[5]);
            f4add(v[6], v[7]); f4add(v[8], v[9]);
            f4add(v[0], v[2]); f4add(v[4], v[6]);
            f4add(v[0], v[4]); f4add(v[0], v[8]);
            const float s = 1.0f / NS2;
            v[0].x *= s; v[0].y *= s; v[0].z *= s; v[0].w *= s;
            uint2 h, l;
            split4(v[0], h, l);
            *(uint2*)(sb + OFF_AH + r * PADB + lane * 8) = h;
            *(uint2*)(sb + OFF_AL + r * PADB + lane * 8) = l;
        }
    }
    CP_ASYNC_WAIT_ALL();
    __syncthreads();

    const char* Ah = sb + OFF_AH;
    const char* Al = sb + OFF_AL;
    const char* Bh = sb + OFF_BH;
    const char* Bl = sb + OFF_BL;

    const int g = lane >> 2;
    const int tg = lane & 3;
    const int wr = (wid >> 2) * 32;   // warp row base
    const int wc = (wid & 3) * 32;    // warp col base

    float acc[2][4][4];
#pragma unroll
    for (int i = 0; i < 2; i++)
#pragma unroll
        for (int j = 0; j < 4; j++)
#pragma unroll
            for (int q = 0; q < 4; q++) acc[i][j][q] = 0.f;

#pragma unroll
    for (int ks = 0; ks < 8; ks++) {
        const int kb = (ks * 16 + tg * 2) * 2;
        uint32_t ah[2][4], al[2][4], bh[4][2], bl[4][2];
#pragma unroll
        for (int i = 0; i < 2; i++) {
            int r = wr + i * 16 + g;
            ah[i][0] = *(const uint32_t*)(Ah + r * PADB + kb);
            ah[i][1] = *(const uint32_t*)(Ah + (r + 8) * PADB + kb);
            ah[i][2] = *(const uint32_t*)(Ah + r * PADB + kb + 16);
            ah[i][3] = *(const uint32_t*)(Ah + (r + 8) * PADB + kb + 16);
            al[i][0] = *(const uint32_t*)(Al + r * PADB + kb);
            al[i][1] = *(const uint32_t*)(Al + (r + 8) * PADB + kb);
            al[i][2] = *(const uint32_t*)(Al + r * PADB + kb + 16);
            al[i][3] = *(const uint32_t*)(Al + (r + 8) * PADB + kb + 16);
        }
#pragma unroll
        for (int j = 0; j < 4; j++) {
            int n = wc + j * 8 + g;
            bh[j][0] = *(const uint32_t*)(Bh + n * PADB + kb);
            bh[j][1] = *(const uint32_t*)(Bh + n * PADB + kb + 16);
            bl[j][0] = *(const uint32_t*)(Bl + n * PADB + kb);
            bl[j][1] = *(const uint32_t*)(Bl + n * PADB + kb + 16);
        }
#pragma unroll
        for (int i = 0; i < 2; i++)
#pragma unroll
            for (int j = 0; j < 4; j++) {
                mma16816(acc[i][j], ah[i], bh[j]);
                mma16816(acc[i][j], al[i], bh[j]);
                mma16816(acc[i][j], ah[i], bl[j]);
            }
    }

    // ---- epilogue: relu + STG.64 into Y1 ----
    const int colg = half * 128 + wc;
#pragma unroll
    for (int i = 0; i < 2; i++) {
        int r = row0 + wr + i * 16 + g;
#pragma unroll
        for (int j = 0; j < 4; j++) {
            int cgl = colg + j * 8 + tg * 2;
            float2 o0, o1;
            o0.x = fmaxf(acc[i][j][0], 0.f);
            o0.y = fmaxf(acc[i][j][1], 0.f);
            o1.x = fmaxf(acc[i][j][2], 0.f);
            o1.y = fmaxf(acc[i][j][3], 0.f);
            *(float2*)(g_Y1 + (size_t)r * 256 + cgl) = o0;
            *(float2*)(g_Y1 + (size_t)(r + 8) * 256 + cgl) = o1;
        }
    }
}

// ---------------- small GEMM + ReLU (tiled, W in smem) ----------------
template <int K>
__global__ __launch_bounds__(256)
void gemm_small_kernel(const float* __restrict__ A0, const float* __restrict__ W0,
                       const float* __restrict__ A1, const float* __restrict__ W1,
                       float* __restrict__ out) {
    extern __shared__ float sm[];
    float* As = sm;             // [K][32] transposed
    float* Bs = sm + K * 32;    // [K][64]

    const int half = blockIdx.y >> 1;
    const float* A = half ? A1 : A0;
    const float* W = half ? W1 : W0;
    const int wcol0 = (blockIdx.y & 1) * 64;
    const int row0 = blockIdx.x * 32;
    const int tid = threadIdx.x;

    for (int idx = tid; idx < 32 * (K / 4); idx += 256) {
        int r  = idx & 31;
        int k4 = (idx >> 5) * 4;
        float4 v = *(const float4*)(A + (size_t)(row0 + r) * 256 + k4);
        As[(k4 + 0) * 32 + r] = v.x;
        As[(k4 + 1) * 32 + r] = v.y;
        As[(k4 + 2) * 32 + r] = v.z;
        As[(k4 + 3) * 32 + r] = v.w;
    }
    for (int idx = tid; idx < K * 16; idx += 256) {
        int k = idx >> 4;
        int j4 = (idx & 15) * 4;
        *(float4*)(Bs + k * 64 + j4) =
            *(const float4*)(W + (size_t)k * 128 + wcol0 + j4);
    }
    __syncthreads();

    const int rr = (tid & 15) * 2;
    const int cc = (tid >> 4) * 4;

    float acc[2][4];
#pragma unroll
    for (int i = 0; i < 2; i++)
#pragma unroll
        for (int j = 0; j < 4; j++) acc[i][j] = 0.f;

#pragma unroll 8
    for (int k = 0; k < K; k++) {
        float2 a = *(const float2*)(As + k * 32 + rr);
        float4 b = *(const float4*)(Bs + k * 64 + cc);
        acc[0][0] = fmaf(a.x, b.x, acc[0][0]);
        acc[0][1] = fmaf(a.x, b.y, acc[0][1]);
        acc[0][2] = fmaf(a.x, b.z, acc[0][2]);
        acc[0][3] = fmaf(a.x, b.w, acc[0][3]);
        acc[1][0] = fmaf(a.y, b.x, acc[1][0]);
        acc[1][1] = fmaf(a.y, b.y, acc[1][1]);
        acc[1][2] = fmaf(a.y, b.z, acc[1][2]);
        acc[1][3] = fmaf(a.y, b.w, acc[1][3]);
    }

    const int ncol = blockIdx.y * 64 + cc;
#pragma unroll
    for (int i = 0; i < 2; i++) {
        float4 o;
        o.x = fmaxf(acc[i][0], 0.f); o.y = fmaxf(acc[i][1], 0.f);
        o.z = fmaxf(acc[i][2], 0.f); o.w = fmaxf(acc[i][3], 0.f);
        *(float4*)(out + (size_t)(row0 + rr + i) * 256 + ncol) = o;
    }
}

// ---------------- mean over S1 of Y1 -> M1 (MLP-batched) ----------------
__global__ void mean25_kernel() {
    int t = blockIdx.x * blockDim.x + threadIdx.x;
    if (t >= NB * 64) return;
    int b = t >> 6;
    int q = t & 63;
    const float4* base = (const float4*)g_Y1 + (size_t)b * NS1 * 64 + q;
    float4 acc = make_float4(0.f, 0.f, 0.f, 0.f);
#pragma unroll
    for (int j0 = 0; j0 < 25; j0 += 5) {
        float4 v[5];
#pragma unroll
        for (int j = 0; j < 5; j++) v[j] = base[(size_t)(j0 + j) * 64];
        f4add(v[0], v[1]); f4add(v[2], v[3]); f4add(v[0], v[2]);
        f4add(v[0], v[4]); f4add(acc, v[0]);
    }
    const float s = 1.0f / NS1;
    acc.x *= s; acc.y *= s; acc.z *= s; acc.w *= s;
    ((float4*)g_M1)[(size_t)b * 64 + q] = acc;
}

// ---------------- launch ----------------
extern "C" void kernel_launch(void* const* d_in, const int* in_sizes, int n_in,
                              void* d_out, int out_size) {
    const float* feat = (const float*)d_in[0];
    const float* ws0  = (const float*)d_in[1];
    const float* wn0  = (const float*)d_in[2];
    const float* ws1  = (const float*)d_in[3];
    const float* wn1  = (const float*)d_in[4];
    const int*   s0   = (const int*)d_in[5];
    const int*   s1   = (const int*)d_in[6];
    const int*   s2   = (const int*)d_in[7];
    float* out = (float*)d_out;

    float *pX0, *pY0, *pM1;
    cudaGetSymbolAddress((void**)&pX0, g_X0);
    cudaGetSymbolAddress((void**)&pY0, g_Y0);
    cudaGetSymbolAddress((void**)&pM1, g_M1);

    const size_t smMMA  = (size_t)(2 * 64 + 2 * 128) * PADB;               // 104448
    const size_t smS128 = (size_t)(128 * 32 + 128 * 64) * sizeof(float);   //  48 KB
    const size_t smS256 = (size_t)(256 * 32 + 256 * 64) * sizeof(float);   //  96 KB
    cudaFuncSetAttribute(gemm_fused_kernel,
                         cudaFuncAttributeMaxDynamicSharedMemorySize, (int)smMMA);
    cudaFuncSetAttribute(gemm_small_kernel<128>,
                         cudaFuncAttributeMaxDynamicSharedMemorySize, (int)smS128);
    cudaFuncSetAttribute(gemm_small_kernel<256>,
                         cudaFuncAttributeMaxDynamicSharedMemorySize, (int)smS256);

    // 1) prep W0/W1 -> transposed bf16 hi/lo
    prep_w_kernel<<<32, 256>>>(ws0, wn0);
    // 2) X0 = [h0 | mean_S1(h1)] (direct from features)
    gather0_kernel<<<(NB * 32 + 255) / 256, 256>>>(feat, s0, s1);
    // 3) Y0 = relu([X0s@Ws0 | X0n@Wn0])
    gemm_small_kernel<128><<<dim3(NB / 32, 4), 256, smS128>>>(pX0, ws0, pX0 + 128, wn0, pY0);
    // 4) Y1 fused gather+GEMM — profiled position
    gemm_fused_kernel<<<dim3(ROWS1 / 64, 2), 256, smMMA>>>(feat, s1, s2);
    // 5) M1 = mean_S1(Y1)
    mean25_kernel<<<(NB * 64 + 255) / 256, 256>>>();
    // 6) out = relu([Y0@Ws1 | M1@Wn1])
    gemm_small_kernel<256><<<dim3(NB / 32, 4), 256, smS256>>>(pY0, ws1, pM1, wn1, out);
}

// round 9
// speedup vs baseline: 1.0858x; 1.0254x over previous
#include <cuda_runtime.h>
#include <cuda_bf16.h>
#include <cstdint>

#define NB   1024
#define NS1  25
#define NS2  10
#define DF   128
#define ROWS1 (NB * NS1)   // 25600

// ---------------- scratch (no allocations allowed) ----------------
__device__ float g_X0[(size_t)NB * 256];
__device__ float g_Y0[(size_t)NB * 256];
__device__ float g_M1[(size_t)NB * 256];     // accumulated mean over s1 (atomic)
__device__ __align__(16) __nv_bfloat16 g_WtH[2 * 128 * 128];  // W^T hi, [half][n][k]
__device__ __align__(16) __nv_bfloat16 g_WtL[2 * 128 * 128];  // W^T lo

// ---------------- helpers ----------------
__device__ __forceinline__ void split4(const float4& v, uint2& hi, uint2& lo) {
    float vv[4] = {v.x, v.y, v.z, v.w};
    uint32_t hp[2], lp[2];
#pragma unroll
    for (int q = 0; q < 2; q++) {
        __nv_bfloat16 h0 = __float2bfloat16(vv[2 * q]);
        __nv_bfloat16 h1 = __float2bfloat16(vv[2 * q + 1]);
        __nv_bfloat16 l0 = __float2bfloat16(vv[2 * q] - __bfloat162float(h0));
        __nv_bfloat16 l1 = __float2bfloat16(vv[2 * q + 1] - __bfloat162float(h1));
        hp[q] = ((uint32_t)__bfloat16_as_ushort(h1) << 16) | __bfloat16_as_ushort(h0);
        lp[q] = ((uint32_t)__bfloat16_as_ushort(l1) << 16) | __bfloat16_as_ushort(l0);
    }
    hi = make_uint2(hp[0], hp[1]);
    lo = make_uint2(lp[0], lp[1]);
}
__device__ __forceinline__ uint32_t smem_to_u32(const void* p) {
    uint32_t a;
    asm("{ .reg .u64 t; cvta.to.shared.u64 t, %1; cvt.u32.u64 %0, t; }"
        : "=r"(a) : "l"(p));
    return a;
}
#define CP_ASYNC16(dst_u32, src_ptr) \
    asm volatile("cp.async.cg.shared.global [%0], [%1], 16;" \
        :: "r"(dst_u32), "l"(src_ptr) : "memory")
#define CP_ASYNC_WAIT_ALL() \
    asm volatile("cp.async.commit_group;\ncp.async.wait_group 0;" ::: "memory")

__device__ __forceinline__ void mma16816(float* c, const uint32_t* a, const uint32_t* b) {
    asm volatile(
        "mma.sync.aligned.m16n8k16.row.col.f32.bf16.bf16.f32 "
        "{%0,%1,%2,%3}, {%4,%5,%6,%7}, {%8,%9}, {%0,%1,%2,%3};"
        : "+f"(c[0]), "+f"(c[1]), "+f"(c[2]), "+f"(c[3])
        : "r"(a[0]), "r"(a[1]), "r"(a[2]), "r"(a[3]), "r"(b[0]), "r"(b[1]));
}
__device__ __forceinline__ void f4add(float4& a, const float4& b) {
    a.x += b.x; a.y += b.y; a.z += b.z; a.w += b.w;
}

// ---------------- zero M1 ----------------
__global__ void zero_m1_kernel() {
    int t = blockIdx.x * blockDim.x + threadIdx.x;
    ((float4*)g_M1)[t] = make_float4(0.f, 0.f, 0.f, 0.f);
}

// ---------------- prep: transpose + bf16-split the layer-0 weights ----------------
__global__ void prep_w_kernel(const float* __restrict__ w0,
                              const float* __restrict__ w1) {
    __shared__ float t[32][33];
    int b = blockIdx.x;
    int half = b >> 4;
    int tile = b & 15;
    int tr = (tile >> 2) * 32;   // k base
    int tc = (tile & 3) * 32;    // n base
    const float* W = half ? w1 : w0;
    int tx = threadIdx.x & 31, ty = threadIdx.x >> 5;   // 32x8
#pragma unroll
    for (int p = 0; p < 32; p += 8)
        t[ty + p][tx] = W[(size_t)(tr + ty + p) * 128 + tc + tx];
    __syncthreads();
#pragma unroll
    for (int p = 0; p < 32; p += 8) {
        int n = tc + ty + p, k = tr + tx;
        float v = t[tx][ty + p];
        __nv_bfloat16 h = __float2bfloat16(v);
        __nv_bfloat16 l = __float2bfloat16(v - __bfloat162float(h));
        size_t o = ((size_t)half * 128 + n) * 128 + k;
        g_WtH[o] = h;
        g_WtL[o] = l;
    }
}

// ---------------- gather0: X0 = [h0 | mean_S1(h1)], MLP-batched ----------------
__global__ void gather0_kernel(const float* __restrict__ feat,
                               const int* __restrict__ s0,
                               const int* __restrict__ s1) {
    int warp = (blockIdx.x * blockDim.x + threadIdx.x) >> 5;
    int lane = threadIdx.x & 31;
    if (warp >= NB) return;
    int c = lane * 4;

    long iself = s0[warp];
    *(float4*)(g_X0 + (size_t)warp * 256 + c) =
        *(const float4*)(feat + iself * DF + c);

    const int* p = s1 + (size_t)warp * NS1;
    int idxs[NS1];
#pragma unroll
    for (int j = 0; j < NS1; j++) idxs[j] = p[j];

    float4 acc = make_float4(0.f, 0.f, 0.f, 0.f);
#pragma unroll
    for (int base = 0; base < 25; base += 5) {
        float4 v[5];
#pragma unroll
        for (int j = 0; j < 5; j++)
            v[j] = *(const float4*)(feat + (long)idxs[base + j] * DF + c);
        f4add(v[0], v[1]); f4add(v[2], v[3]); f4add(v[0], v[2]);
        f4add(v[0], v[4]); f4add(acc, v[0]);
    }
    const float s = 1.0f / NS1;
    acc.x *= s; acc.y *= s; acc.z *= s; acc.w *= s;
    *(float4*)(g_X0 + (size_t)warp * 256 + 128 + c) = acc;
}

// ---------------- fused gather + GEMM (HMMA bf16x3) -> atomic mean into M1 ----------------
// 1D grid of 800: half = bid & 1 (wave-balanced), 64 rows per CTA.
#define PADB 272   // smem row pitch in bytes

__global__ __launch_bounds__(256, 2)
void gemm_fused_kernel(const float* __restrict__ feat,
                       const int* __restrict__ s1,
                       const int* __restrict__ s2) {
    extern __shared__ char sb[];
    const uint32_t OFF_AH = 0;
    const uint32_t OFF_AL = 64 * PADB;
    const uint32_t OFF_BH = 2 * 64 * PADB;
    const uint32_t OFF_BL = OFF_BH + 128 * PADB;
    const uint32_t smb = smem_to_u32(sb);

    const int half = blockIdx.x & 1;
    const int row0 = (blockIdx.x >> 1) * 64;
    const int tid = threadIdx.x;
    const int wid = tid >> 5;
    const int lane = tid & 31;

    // ---- stage B first (async, overlaps the A gather) ----
    for (int idx = tid; idx < 2048; idx += 256) {
        int n = idx >> 4;
        int ch = (idx & 15) * 16;
        size_t gsrc = (size_t)half * 16384 + (size_t)n * 128;
        uint32_t dst = n * PADB + ch;
        CP_ASYNC16(smb + OFF_BH + dst, (const char*)(g_WtH + gsrc) + ch);
        CP_ASYNC16(smb + OFF_BL + dst, (const char*)(g_WtL + gsrc) + ch);
    }

    // ---- gather A: 8 rows per warp, loads explicitly batched for MLP ----
    const int c = lane * 4;
    if (half == 0) {
        long idxs[8];
#pragma unroll
        for (int it = 0; it < 8; it++) idxs[it] = s1[row0 + wid + it * 8];
        float4 v[8];
#pragma unroll
        for (int it = 0; it < 8; it++)
            v[it] = *(const float4*)(feat + idxs[it] * DF + c);
#pragma unroll
        for (int it = 0; it < 8; it++) {
            const int r = wid + it * 8;
            uint2 h, l;
            split4(v[it], h, l);
            *(uint2*)(sb + OFF_AH + r * PADB + lane * 8) = h;
            *(uint2*)(sb + OFF_AL + r * PADB + lane * 8) = l;
        }
    } else {
#pragma unroll
        for (int it = 0; it < 8; it++) {
            const int r = wid + it * 8;
            const int gr = row0 + r;
            const int* p = s2 + (size_t)gr * NS2;
            int idxs[NS2];
#pragma unroll
            for (int j = 0; j < NS2; j++) idxs[j] = p[j];
            float4 v[NS2];
#pragma unroll
            for (int j = 0; j < NS2; j++)
                v[j] = *(const float4*)(feat + (long)idxs[j] * DF + c);
            f4add(v[0], v[1]); f4add(v[2], v[3]); f4add(v[4], v[5]);
            f4add(v[6], v[7]); f4add(v[8], v[9]);
            f4add(v[0], v[2]); f4add(v[4], v[6]);
            f4add(v[0], v[4]); f4add(v[0], v[8]);
            const float s = 1.0f / NS2;
            v[0].x *= s; v[0].y *= s; v[0].z *= s; v[0].w *= s;
            uint2 h, l;
            split4(v[0], h, l);
            *(uint2*)(sb + OFF_AH + r * PADB + lane * 8) = h;
            *(uint2*)(sb + OFF_AL + r * PADB + lane * 8) = l;
        }
    }
    CP_ASYNC_WAIT_ALL();
    __syncthreads();

    const char* Ah = sb + OFF_AH;
    const char* Al = sb + OFF_AL;
    const char* Bh = sb + OFF_BH;
    const char* Bl = sb + OFF_BL;

    const int g = lane >> 2;
    const int tg = lane & 3;
    const int wr = (wid >> 2) * 32;   // warp row base
    const int wc = (wid & 3) * 32;    // warp col base

    float acc[2][4][4];
#pragma unroll
    for (int i = 0; i < 2; i++)
#pragma unroll
        for (int j = 0; j < 4; j++)
#pragma unroll
            for (int q = 0; q < 4; q++) acc[i][j][q] = 0.f;

#pragma unroll
    for (int ks = 0; ks < 8; ks++) {
        const int kb = (ks * 16 + tg * 2) * 2;
        uint32_t ah[2][4], al[2][4], bh[4][2], bl[4][2];
#pragma unroll
        for (int i = 0; i < 2; i++) {
            int r = wr + i * 16 + g;
            ah[i][0] = *(const uint32_t*)(Ah + r * PADB + kb);
            ah[i][1] = *(const uint32_t*)(Ah + (r + 8) * PADB + kb);
            ah[i][2] = *(const uint32_t*)(Ah + r * PADB + kb + 16);
            ah[i][3] = *(const uint32_t*)(Ah + (r + 8) * PADB + kb + 16);
            al[i][0] = *(const uint32_t*)(Al + r * PADB + kb);
            al[i][1] = *(const uint32_t*)(Al + (r + 8) * PADB + kb);
            al[i][2] = *(const uint32_t*)(Al + r * PADB + kb + 16);
            al[i][3] = *(const uint32_t*)(Al + (r + 8) * PADB + kb + 16);
        }
#pragma unroll
        for (int j = 0; j < 4; j++) {
            int n = wc + j * 8 + g;
            bh[j][0] = *(const uint32_t*)(Bh + n * PADB + kb);
            bh[j][1] = *(const uint32_t*)(Bh + n * PADB + kb + 16);
            bl[j][0] = *(const uint32_t*)(Bl + n * PADB + kb);
            bl[j][1] = *(const uint32_t*)(Bl + n * PADB + kb + 16);
        }
#pragma unroll
        for (int i = 0; i < 2; i++)
#pragma unroll
            for (int j = 0; j < 4; j++) {
                mma16816(acc[i][j], ah[i], bh[j]);
                mma16816(acc[i][j], al[i], bh[j]);
                mma16816(acc[i][j], ah[i], bl[j]);
            }
    }

    // ---- epilogue: relu, scale 1/25, atomic-accumulate into M1[b][col] ----
    const int colg = half * 128 + wc;
    const float inv25 = 1.0f / NS1;
#pragma unroll
    for (int i = 0; i < 2; i++) {
        int r0g = row0 + wr + i * 16 + g;
        int b0 = r0g / NS1;
        int b1 = (r0g + 8) / NS1;
#pragma unroll
        for (int j = 0; j < 4; j++) {
            int cgl = colg + j * 8 + tg * 2;
            float v0 = fmaxf(acc[i][j][0], 0.f) * inv25;
            float v1 = fmaxf(acc[i][j][1], 0.f) * inv25;
            float v2 = fmaxf(acc[i][j][2], 0.f) * inv25;
            float v3 = fmaxf(acc[i][j][3], 0.f) * inv25;
            atomicAdd(&g_M1[(size_t)b0 * 256 + cgl],     v0);
            atomicAdd(&g_M1[(size_t)b0 * 256 + cgl + 1], v1);
            atomicAdd(&g_M1[(size_t)b1 * 256 + cgl],     v2);
            atomicAdd(&g_M1[(size_t)b1 * 256 + cgl + 1], v3);
        }
    }
}

// ---------------- small GEMM + ReLU (tiled, W in smem) ----------------
template <int K>
__global__ __launch_bounds__(256)
void gemm_small_kernel(const float* __restrict__ A0, const float* __restrict__ W0,
                       const float* __restrict__ A1, const float* __restrict__ W1,
                       float* __restrict__ out) {
    extern __shared__ float sm[];
    float* As = sm;             // [K][32] transposed
    float* Bs = sm + K * 32;    // [K][64]

    const int half = blockIdx.y >> 1;
    const float* A = half ? A1 : A0;
    const float* W = half ? W1 : W0;
    const int wcol0 = (blockIdx.y & 1) * 64;
    const int row0 = blockIdx.x * 32;
    const int tid = threadIdx.x;

    for (int idx = tid; idx < 32 * (K / 4); idx += 256) {
        int r  = idx & 31;
        int k4 = (idx >> 5) * 4;
        float4 v = *(const float4*)(A + (size_t)(row0 + r) * 256 + k4);
        As[(k4 + 0) * 32 + r] = v.x;
        As[(k4 + 1) * 32 + r] = v.y;
        As[(k4 + 2) * 32 + r] = v.z;
        As[(k4 + 3) * 32 + r] = v.w;
    }
    for (int idx = tid; idx < K * 16; idx += 256) {
        int k = idx >> 4;
        int j4 = (idx & 15) * 4;
        *(float4*)(Bs + k * 64 + j4) =
            *(const float4*)(W + (size_t)k * 128 + wcol0 + j4);
    }
    __syncthreads();

    const int rr = (tid & 15) * 2;
    const int cc = (tid >> 4) * 4;

    float acc[2][4];
#pragma unroll
    for (int i = 0; i < 2; i++)
#pragma unroll
        for (int j = 0; j < 4; j++) acc[i][j] = 0.f;

#pragma unroll 8
    for (int k = 0; k < K; k++) {
        float2 a = *(const float2*)(As + k * 32 + rr);
        float4 b = *(const float4*)(Bs + k * 64 + cc);
        acc[0][0] = fmaf(a.x, b.x, acc[0][0]);
        acc[0][1] = fmaf(a.x, b.y, acc[0][1]);
        acc[0][2] = fmaf(a.x, b.z, acc[0][2]);
        acc[0][3] = fmaf(a.x, b.w, acc[0][3]);
        acc[1][0] = fmaf(a.y, b.x, acc[1][0]);
        acc[1][1] = fmaf(a.y, b.y, acc[1][1]);
        acc[1][2] = fmaf(a.y, b.z, acc[1][2]);
        acc[1][3] = fmaf(a.y, b.w, acc[1][3]);
    }

    const int ncol = blockIdx.y * 64 + cc;
#pragma unroll
    for (int i = 0; i < 2; i++) {
        float4 o;
        o.x = fmaxf(acc[i][0], 0.f); o.y = fmaxf(acc[i][1], 0.f);
        o.z = fmaxf(acc[i][2], 0.f); o.w = fmaxf(acc[i][3], 0.f);
        *(float4*)(out + (size_t)(row0 + rr + i) * 256 + ncol) = o;
    }
}

// ---------------- launch ----------------
extern "C" void kernel_launch(void* const* d_in, const int* in_sizes, int n_in,
                              void* d_out, int out_size) {
    const float* feat = (const float*)d_in[0];
    const float* ws0  = (const float*)d_in[1];
    const float* wn0  = (const float*)d_in[2];
    const float* ws1  = (const float*)d_in[3];
    const float* wn1  = (const float*)d_in[4];
    const int*   s0   = (const int*)d_in[5];
    const int*   s1   = (const int*)d_in[6];
    const int*   s2   = (const int*)d_in[7];
    float* out = (float*)d_out;

    float *pX0, *pY0, *pM1;
    cudaGetSymbolAddress((void**)&pX0, g_X0);
    cudaGetSymbolAddress((void**)&pY0, g_Y0);
    cudaGetSymbolAddress((void**)&pM1, g_M1);

    const size_t smMMA  = (size_t)(2 * 64 + 2 * 128) * PADB;               // 104448
    const size_t smS128 = (size_t)(128 * 32 + 128 * 64) * sizeof(float);   //  48 KB
    const size_t smS256 = (size_t)(256 * 32 + 256 * 64) * sizeof(float);   //  96 KB
    cudaFuncSetAttribute(gemm_fused_kernel,
                         cudaFuncAttributeMaxDynamicSharedMemorySize, (int)smMMA);
    cudaFuncSetAttribute(gemm_small_kernel<128>,
                         cudaFuncAttributeMaxDynamicSharedMemorySize, (int)smS128);
    cudaFuncSetAttribute(gemm_small_kernel<256>,
                         cudaFuncAttributeMaxDynamicSharedMemorySize, (int)smS256);

    // 1) prep W0/W1 -> transposed bf16 hi/lo; zero M1 accumulator
    prep_w_kernel<<<32, 256>>>(ws0, wn0);
    zero_m1_kernel<<<NB * 64 / 256, 256>>>();
    // 2) X0 = [h0 | mean_S1(h1)]
    gather0_kernel<<<(NB * 32 + 255) / 256, 256>>>(feat, s0, s1);
    // 3) Y0 = relu([X0s@Ws0 | X0n@Wn0])
    gemm_small_kernel<128><<<dim3(NB / 32, 4), 256, smS128>>>(pX0, ws0, pX0 + 128, wn0, pY0);
    // 4) fused gather + GEMM + atomic mean -> M1   (profiled position)
    gemm_fused_kernel<<<2 * (ROWS1 / 64), 256, smMMA>>>(feat, s1, s2);
    // 5) out = relu([Y0@Ws1 | M1@Wn1])
    gemm_small_kernel<256><<<dim3(NB / 32, 4), 256, smS256>>>(pY0, ws1, pM1, wn1, out);
}

// round 10
// speedup vs baseline: 1.1162x; 1.0280x over previous
#include <cuda_runtime.h>
#include <cuda_bf16.h>
#include <cstdint>

#define NB   1024
#define NS1  25
#define NS2  10
#define DF   128
#define ROWS1 (NB * NS1)   // 25600

// ---------------- scratch (no allocations allowed) ----------------
__device__ float g_X0[(size_t)NB * 256];
__device__ float g_Y0[(size_t)NB * 256];
__device__ float g_M1[(size_t)NB * 256];     // accumulated mean over s1 (atomic)
__device__ __align__(16) __nv_bfloat16 g_WtH[2 * 128 * 128];  // W^T hi, [half][n][k]
__device__ __align__(16) __nv_bfloat16 g_WtL[2 * 128 * 128];  // W^T lo

// ---------------- helpers ----------------
__device__ __forceinline__ void split4(const float4& v, uint2& hi, uint2& lo) {
    float vv[4] = {v.x, v.y, v.z, v.w};
    uint32_t hp[2], lp[2];
#pragma unroll
    for (int q = 0; q < 2; q++) {
        __nv_bfloat16 h0 = __float2bfloat16(vv[2 * q]);
        __nv_bfloat16 h1 = __float2bfloat16(vv[2 * q + 1]);
        __nv_bfloat16 l0 = __float2bfloat16(vv[2 * q] - __bfloat162float(h0));
        __nv_bfloat16 l1 = __float2bfloat16(vv[2 * q + 1] - __bfloat162float(h1));
        hp[q] = ((uint32_t)__bfloat16_as_ushort(h1) << 16) | __bfloat16_as_ushort(h0);
        lp[q] = ((uint32_t)__bfloat16_as_ushort(l1) << 16) | __bfloat16_as_ushort(l0);
    }
    hi = make_uint2(hp[0], hp[1]);
    lo = make_uint2(lp[0], lp[1]);
}
__device__ __forceinline__ uint32_t smem_to_u32(const void* p) {
    uint32_t a;
    asm("{ .reg .u64 t; cvta.to.shared.u64 t, %1; cvt.u32.u64 %0, t; }"
        : "=r"(a) : "l"(p));
    return a;
}
#define CP_ASYNC16(dst_u32, src_ptr) \
    asm volatile("cp.async.cg.shared.global [%0], [%1], 16;" \
        :: "r"(dst_u32), "l"(src_ptr) : "memory")
#define CP_ASYNC_WAIT_ALL() \
    asm volatile("cp.async.commit_group;\ncp.async.wait_group 0;" ::: "memory")

__device__ __forceinline__ void mma16816(float* c, const uint32_t* a, const uint32_t* b) {
    asm volatile(
        "mma.sync.aligned.m16n8k16.row.col.f32.bf16.bf16.f32 "
        "{%0,%1,%2,%3}, {%4,%5,%6,%7}, {%8,%9}, {%0,%1,%2,%3};"
        : "+f"(c[0]), "+f"(c[1]), "+f"(c[2]), "+f"(c[3])
        : "r"(a[0]), "r"(a[1]), "r"(a[2]), "r"(a[3]), "r"(b[0]), "r"(b[1]));
}
__device__ __forceinline__ void f4add(float4& a, const float4& b) {
    a.x += b.x; a.y += b.y; a.z += b.z; a.w += b.w;
}

// ---------------- zero M1 + out ----------------
__global__ void zero_kernel(float* __restrict__ out) {
    int t = blockIdx.x * blockDim.x + threadIdx.x;   // 512*256 = 131072
    if (t < 65536) ((float4*)g_M1)[t] = make_float4(0.f, 0.f, 0.f, 0.f);
    else ((float4*)out)[t - 65536] = make_float4(0.f, 0.f, 0.f, 0.f);
}

// ---------------- prep: transpose + bf16-split the layer-0 weights ----------------
__global__ void prep_w_kernel(const float* __restrict__ w0,
                              const float* __restrict__ w1) {
    __shared__ float t[32][33];
    int b = blockIdx.x;
    int half = b >> 4;
    int tile = b & 15;
    int tr = (tile >> 2) * 32;   // k base
    int tc = (tile & 3) * 32;    // n base
    const float* W = half ? w1 : w0;
    int tx = threadIdx.x & 31, ty = threadIdx.x >> 5;   // 32x8
#pragma unroll
    for (int p = 0; p < 32; p += 8)
        t[ty + p][tx] = W[(size_t)(tr + ty + p) * 128 + tc + tx];
    __syncthreads();
#pragma unroll
    for (int p = 0; p < 32; p += 8) {
        int n = tc + ty + p, k = tr + tx;
        float v = t[tx][ty + p];
        __nv_bfloat16 h = __float2bfloat16(v);
        __nv_bfloat16 l = __float2bfloat16(v - __bfloat162float(h));
        size_t o = ((size_t)half * 128 + n) * 128 + k;
        g_WtH[o] = h;
        g_WtL[o] = l;
    }
}

// ---------------- mega kernel: 32 gather0 blocks + 800 fused gather/GEMM blocks ----------------
#define PADB 272   // smem row pitch in bytes
#define G0_BLOCKS 32

__global__ __launch_bounds__(256, 2)
void mega_kernel(const float* __restrict__ feat,
                 const int* __restrict__ s0,
                 const int* __restrict__ s1,
                 const int* __restrict__ s2) {
    const int tid = threadIdx.x;
    const int wid = tid >> 5;
    const int lane = tid & 31;
    const int c = lane * 4;

    if (blockIdx.x < G0_BLOCKS) {
        // ---- gather0: X0 = [h0 | mean_S1(h1)]; warp handles 4 rows ----
        int wg = blockIdx.x * 8 + wid;    // 0..255
#pragma unroll
        for (int i = 0; i < 4; i++) {
            int row = wg * 4 + i;
            long iself = s0[row];
            *(float4*)(g_X0 + (size_t)row * 256 + c) =
                *(const float4*)(feat + iself * DF + c);

            const int* p = s1 + (size_t)row * NS1;
            int idxs[NS1];
#pragma unroll
            for (int j = 0; j < NS1; j++) idxs[j] = p[j];
            float4 acc = make_float4(0.f, 0.f, 0.f, 0.f);
#pragma unroll
            for (int base = 0; base < 25; base += 5) {
                float4 v[5];
#pragma unroll
                for (int j = 0; j < 5; j++)
                    v[j] = *(const float4*)(feat + (long)idxs[base + j] * DF + c);
                f4add(v[0], v[1]); f4add(v[2], v[3]); f4add(v[0], v[2]);
                f4add(v[0], v[4]); f4add(acc, v[0]);
            }
            const float s = 1.0f / NS1;
            acc.x *= s; acc.y *= s; acc.z *= s; acc.w *= s;
            *(float4*)(g_X0 + (size_t)row * 256 + 128 + c) = acc;
        }
        return;
    }

    // ---- fused gather + HMMA bf16x3 + atomic mean into M1 ----
    extern __shared__ char sb[];
    const uint32_t OFF_AH = 0;
    const uint32_t OFF_AL = 64 * PADB;
    const uint32_t OFF_BH = 2 * 64 * PADB;
    const uint32_t OFF_BL = OFF_BH + 128 * PADB;
    const uint32_t smb = smem_to_u32(sb);

    const int bid2 = blockIdx.x - G0_BLOCKS;
    const int half = bid2 & 1;
    const int row0 = (bid2 >> 1) * 64;

    for (int idx = tid; idx < 2048; idx += 256) {
        int n = idx >> 4;
        int ch = (idx & 15) * 16;
        size_t gsrc = (size_t)half * 16384 + (size_t)n * 128;
        uint32_t dst = n * PADB + ch;
        CP_ASYNC16(smb + OFF_BH + dst, (const char*)(g_WtH + gsrc) + ch);
        CP_ASYNC16(smb + OFF_BL + dst, (const char*)(g_WtL + gsrc) + ch);
    }

    if (half == 0) {
        long idxs[8];
#pragma unroll
        for (int it = 0; it < 8; it++) idxs[it] = s1[row0 + wid + it * 8];
        float4 v[8];
#pragma unroll
        for (int it = 0; it < 8; it++)
            v[it] = *(const float4*)(feat + idxs[it] * DF + c);
#pragma unroll
        for (int it = 0; it < 8; it++) {
            const int r = wid + it * 8;
            uint2 h, l;
            split4(v[it], h, l);
            *(uint2*)(sb + OFF_AH + r * PADB + lane * 8) = h;
            *(uint2*)(sb + OFF_AL + r * PADB + lane * 8) = l;
        }
    } else {
#pragma unroll
        for (int it = 0; it < 8; it++) {
            const int r = wid + it * 8;
            const int gr = row0 + r;
            const int* p = s2 + (size_t)gr * NS2;
            int idxs[NS2];
#pragma unroll
            for (int j = 0; j < NS2; j++) idxs[j] = p[j];
            float4 v[NS2];
#pragma unroll
            for (int j = 0; j < NS2; j++)
                v[j] = *(const float4*)(feat + (long)idxs[j] * DF + c);
            f4add(v[0], v[1]); f4add(v[2], v[3]); f4add(v[4], v[5]);
            f4add(v[6], v[7]); f4add(v[8], v[9]);
            f4add(v[0], v[2]); f4add(v[4], v[6]);
            f4add(v[0], v[4]); f4add(v[0], v[8]);
            const float s = 1.0f / NS2;
            v[0].x *= s; v[0].y *= s; v[0].z *= s; v[0].w *= s;
            uint2 h, l;
            split4(v[0], h, l);
            *(uint2*)(sb + OFF_AH + r * PADB + lane * 8) = h;
            *(uint2*)(sb + OFF_AL + r * PADB + lane * 8) = l;
        }
    }
    CP_ASYNC_WAIT_ALL();
    __syncthreads();

    const char* Ah = sb + OFF_AH;
    const char* Al = sb + OFF_AL;
    const char* Bh = sb + OFF_BH;
    const char* Bl = sb + OFF_BL;

    const int g = lane >> 2;
    const int tg = lane & 3;
    const int wr = (wid >> 2) * 32;
    const int wc = (wid & 3) * 32;

    float acc[2][4][4];
#pragma unroll
    for (int i = 0; i < 2; i++)
#pragma unroll
        for (int j = 0; j < 4; j++)
#pragma unroll
            for (int q = 0; q < 4; q++) acc[i][j][q] = 0.f;

#pragma unroll
    for (int ks = 0; ks < 8; ks++) {
        const int kb = (ks * 16 + tg * 2) * 2;
        uint32_t ah[2][4], al[2][4], bh[4][2], bl[4][2];
#pragma unroll
        for (int i = 0; i < 2; i++) {
            int r = wr + i * 16 + g;
            ah[i][0] = *(const uint32_t*)(Ah + r * PADB + kb);
            ah[i][1] = *(const uint32_t*)(Ah + (r + 8) * PADB + kb);
            ah[i][2] = *(const uint32_t*)(Ah + r * PADB + kb + 16);
            ah[i][3] = *(const uint32_t*)(Ah + (r + 8) * PADB + kb + 16);
            al[i][0] = *(const uint32_t*)(Al + r * PADB + kb);
            al[i][1] = *(const uint32_t*)(Al + (r + 8) * PADB + kb);
            al[i][2] = *(const uint32_t*)(Al + r * PADB + kb + 16);
            al[i][3] = *(const uint32_t*)(Al + (r + 8) * PADB + kb + 16);
        }
#pragma unroll
        for (int j = 0; j < 4; j++) {
            int n = wc + j * 8 + g;
            bh[j][0] = *(const uint32_t*)(Bh + n * PADB + kb);
            bh[j][1] = *(const uint32_t*)(Bh + n * PADB + kb + 16);
            bl[j][0] = *(const uint32_t*)(Bl + n * PADB + kb);
            bl[j][1] = *(const uint32_t*)(Bl + n * PADB + kb + 16);
        }
#pragma unroll
        for (int i = 0; i < 2; i++)
#pragma unroll
            for (int j = 0; j < 4; j++) {
                mma16816(acc[i][j], ah[i], bh[j]);
                mma16816(acc[i][j], al[i], bh[j]);
                mma16816(acc[i][j], ah[i], bl[j]);
            }
    }

    const int colg = half * 128 + wc;
    const float inv25 = 1.0f / NS1;
#pragma unroll
    for (int i = 0; i < 2; i++) {
        int r0g = row0 + wr + i * 16 + g;
        int b0 = r0g / NS1;
        int b1 = (r0g + 8) / NS1;
#pragma unroll
        for (int j = 0; j < 4; j++) {
            int cgl = colg + j * 8 + tg * 2;
            atomicAdd(&g_M1[(size_t)b0 * 256 + cgl],     fmaxf(acc[i][j][0], 0.f) * inv25);
            atomicAdd(&g_M1[(size_t)b0 * 256 + cgl + 1], fmaxf(acc[i][j][1], 0.f) * inv25);
            atomicAdd(&g_M1[(size_t)b1 * 256 + cgl],     fmaxf(acc[i][j][2], 0.f) * inv25);
            atomicAdd(&g_M1[(size_t)b1 * 256 + cgl + 1], fmaxf(acc[i][j][3], 0.f) * inv25);
        }
    }
}

// ---------------- layer-0 small GEMM: Y0 = relu([X0s@Ws0 | X0n@Wn0]) ----------------
// grid (64, 4): bx = 16-row tile, by = 64-col chunk (by<2: self, else neigh).
// block 256 thr: thread = (row = tid&15, cols = (tid>>4)*4). K=128 smem-resident.
__global__ __launch_bounds__(256)
void small_l0_kernel(const float* __restrict__ ws0, const float* __restrict__ wn0) {
    __shared__ float As[128 * 16];   // [k][r]
    __shared__ float Bs[128 * 64];   // [k][c]
    const int by = blockIdx.y;
    const int row0 = blockIdx.x * 16;
    const float* W = (by < 2) ? ws0 : wn0;
    const int aoff = (by < 2) ? 0 : 128;
    const int wcol0 = (by & 1) * 64;
    const int tid = threadIdx.x;

    for (int idx = tid; idx < 16 * 32; idx += 256) {
        int r = idx >> 5;
        int k4 = (idx & 31) * 4;
        float4 v = *(const float4*)(g_X0 + (size_t)(row0 + r) * 256 + aoff + k4);
        As[(k4 + 0) * 16 + r] = v.x;
        As[(k4 + 1) * 16 + r] = v.y;
        As[(k4 + 2) * 16 + r] = v.z;
        As[(k4 + 3) * 16 + r] = v.w;
    }
    for (int idx = tid; idx < 128 * 16; idx += 256) {
        int k = idx >> 4;
        int j4 = (idx & 15) * 4;
        *(float4*)(Bs + k * 64 + j4) =
            *(const float4*)(W + (size_t)k * 128 + wcol0 + j4);
    }
    __syncthreads();

    const int r = tid & 15;
    const int c4 = (tid >> 4) * 4;
    float a0 = 0.f, a1 = 0.f, a2 = 0.f, a3 = 0.f;
#pragma unroll 8
    for (int k = 0; k < 128; k++) {
        float a = As[k * 16 + r];
        float4 b = *(const float4*)(Bs + k * 64 + c4);
        a0 = fmaf(a, b.x, a0); a1 = fmaf(a, b.y, a1);
        a2 = fmaf(a, b.z, a2); a3 = fmaf(a, b.w, a3);
    }
    float4 o;
    o.x = fmaxf(a0, 0.f); o.y = fmaxf(a1, 0.f);
    o.z = fmaxf(a2, 0.f); o.w = fmaxf(a3, 0.f);
    *(float4*)(g_Y0 + (size_t)(row0 + r) * 256 + by * 64 + c4) = o;
}

// ---------------- layer-1 small GEMM: out += [Y0@Ws1 | M1@Wn1] (K split x2) ----------------
// grid (64, 8): by&3 = 64-col chunk, by>>2 = k-chunk (128 each). atomicAdd into out.
__global__ __launch_bounds__(256)
void small_l1_kernel(const float* __restrict__ ws1, const float* __restrict__ wn1,
                     float* __restrict__ out) {
    __shared__ float As[128 * 16];
    __shared__ float Bs[128 * 64];
    const int cchunk = blockIdx.y & 3;
    const int kc = blockIdx.y >> 2;
    const int row0 = blockIdx.x * 16;
    const float* A = (cchunk < 2) ? g_Y0 : g_M1;
    const float* W = (cchunk < 2) ? ws1 : wn1;
    const int wcol0 = (cchunk & 1) * 64;
    const int tid = threadIdx.x;

    for (int idx = tid; idx < 16 * 32; idx += 256) {
        int r = idx >> 5;
        int k4 = (idx & 31) * 4;
        float4 v = *(const float4*)(A + (size_t)(row0 + r) * 256 + kc * 128 + k4);
        As[(k4 + 0) * 16 + r] = v.x;
        As[(k4 + 1) * 16 + r] = v.y;
        As[(k4 + 2) * 16 + r] = v.z;
        As[(k4 + 3) * 16 + r] = v.w;
    }
    for (int idx = tid; idx < 128 * 16; idx += 256) {
        int k = idx >> 4;
        int j4 = (idx & 15) * 4;
        *(float4*)(Bs + k * 64 + j4) =
            *(const float4*)(W + (size_t)(kc * 128 + k) * 128 + wcol0 + j4);
    }
    __syncthreads();

    const int r = tid & 15;
    const int c4 = (tid >> 4) * 4;
    float a0 = 0.f, a1 = 0.f, a2 = 0.f, a3 = 0.f;
#pragma unroll 8
    for (int k = 0; k < 128; k++) {
        float a = As[k * 16 + r];
        float4 b = *(const float4*)(Bs + k * 64 + c4);
        a0 = fmaf(a, b.x, a0); a1 = fmaf(a, b.y, a1);
        a2 = fmaf(a, b.z, a2); a3 = fmaf(a, b.w, a3);
    }
    float* orow = out + (size_t)(row0 + r) * 256 + cchunk * 64 + c4;
    atomicAdd(orow + 0, a0);
    atomicAdd(orow + 1, a1);
    atomicAdd(orow + 2, a2);
    atomicAdd(orow + 3, a3);
}

// ---------------- final relu over out ----------------
__global__ void relu_kernel(float* __restrict__ out) {
    int t = blockIdx.x * blockDim.x + threadIdx.x;   // 65536
    float4 v = ((float4*)out)[t];
    v.x = fmaxf(v.x, 0.f); v.y = fmaxf(v.y, 0.f);
    v.z = fmaxf(v.z, 0.f); v.w = fmaxf(v.w, 0.f);
    ((float4*)out)[t] = v;
}

// ---------------- launch ----------------
extern "C" void kernel_launch(void* const* d_in, const int* in_sizes, int n_in,
                              void* d_out, int out_size) {
    const float* feat = (const float*)d_in[0];
    const float* ws0  = (const float*)d_in[1];
    const float* wn0  = (const float*)d_in[2];
    const float* ws1  = (const float*)d_in[3];
    const float* wn1  = (const float*)d_in[4];
    const int*   s0   = (const int*)d_in[5];
    const int*   s1   = (const int*)d_in[6];
    const int*   s2   = (const int*)d_in[7];
    float* out = (float*)d_out;

    const size_t smMMA = (size_t)(2 * 64 + 2 * 128) * PADB;   // 104448
    cudaFuncSetAttribute(mega_kernel,
                         cudaFuncAttributeMaxDynamicSharedMemorySize, (int)smMMA);

    // 1) prep W0/W1 -> transposed bf16 hi/lo
    prep_w_kernel<<<32, 256>>>(ws0, wn0);
    // 2) zero M1 + out
    zero_kernel<<<512, 256>>>(out);
    // 3) mega: gather0 (32 blocks) + fused gather/GEMM/atomic-mean (800 blocks)
    mega_kernel<<<G0_BLOCKS + 2 * (ROWS1 / 64), 256, smMMA>>>(feat, s0, s1, s2);
    // 4) Y0 = relu([X0s@Ws0 | X0n@Wn0])
    small_l0_kernel<<<dim3(64, 4), 256>>>(ws0, wn0);
    // 5) out += [Y0@Ws1 | M1@Wn1]  (K split, atomic)
    small_l1_kernel<<<dim3(64, 8), 256>>>(ws1, wn1, out);
    // 6) relu(out)
    relu_kernel<<<256, 256>>>(out);
}

// round 11
// speedup vs baseline: 1.2562x; 1.1255x over previous
#include <cuda_runtime.h>
#include <cuda_bf16.h>
#include <cstdint>

#define NB   1024
#define NS1  25
#define NS2  10
#define DF   128
#define ROWS1 (NB * NS1)   // 25600

// ---------------- scratch (no allocations allowed) ----------------
__device__ float g_X0[(size_t)NB * 256];
__device__ float g_Y0[(size_t)NB * 256];
__device__ float g_M1[(size_t)NB * 256];     // accumulated mean over s1 (atomic)
// W^T bf16 hi/lo: [ws0: 128n x 128k @0][wn0: @16384][ws1: 128n x 256k @32768][wn1: @65536]
__device__ __align__(16) __nv_bfloat16 g_WtH[98304];
__device__ __align__(16) __nv_bfloat16 g_WtL[98304];

// ---------------- helpers ----------------
__device__ __forceinline__ void split4(const float4& v, uint2& hi, uint2& lo) {
    float vv[4] = {v.x, v.y, v.z, v.w};
    uint32_t hp[2], lp[2];
#pragma unroll
    for (int q = 0; q < 2; q++) {
        __nv_bfloat16 h0 = __float2bfloat16(vv[2 * q]);
        __nv_bfloat16 h1 = __float2bfloat16(vv[2 * q + 1]);
        __nv_bfloat16 l0 = __float2bfloat16(vv[2 * q] - __bfloat162float(h0));
        __nv_bfloat16 l1 = __float2bfloat16(vv[2 * q + 1] - __bfloat162float(h1));
        hp[q] = ((uint32_t)__bfloat16_as_ushort(h1) << 16) | __bfloat16_as_ushort(h0);
        lp[q] = ((uint32_t)__bfloat16_as_ushort(l1) << 16) | __bfloat16_as_ushort(l0);
    }
    hi = make_uint2(hp[0], hp[1]);
    lo = make_uint2(lp[0], lp[1]);
}
__device__ __forceinline__ uint32_t smem_to_u32(const void* p) {
    uint32_t a;
    asm("{ .reg .u64 t; cvta.to.shared.u64 t, %1; cvt.u32.u64 %0, t; }"
        : "=r"(a) : "l"(p));
    return a;
}
#define CP_ASYNC16(dst_u32, src_ptr) \
    asm volatile("cp.async.cg.shared.global [%0], [%1], 16;" \
        :: "r"(dst_u32), "l"(src_ptr) : "memory")
#define CP_ASYNC_WAIT_ALL() \
    asm volatile("cp.async.commit_group;\ncp.async.wait_group 0;" ::: "memory")

__device__ __forceinline__ void mma16816(float* c, const uint32_t* a, const uint32_t* b) {
    asm volatile(
        "mma.sync.aligned.m16n8k16.row.col.f32.bf16.bf16.f32 "
        "{%0,%1,%2,%3}, {%4,%5,%6,%7}, {%8,%9}, {%0,%1,%2,%3};"
        : "+f"(c[0]), "+f"(c[1]), "+f"(c[2]), "+f"(c[3])
        : "r"(a[0]), "r"(a[1]), "r"(a[2]), "r"(a[3]), "r"(b[0]), "r"(b[1]));
}
__device__ __forceinline__ void f4add(float4& a, const float4& b) {
    a.x += b.x; a.y += b.y; a.z += b.z; a.w += b.w;
}

// ---------------- zero M1 ----------------
__global__ void zero_m1_kernel() {
    int t = blockIdx.x * blockDim.x + threadIdx.x;
    ((float4*)g_M1)[t] = make_float4(0.f, 0.f, 0.f, 0.f);
}

// ---------------- prep: transpose + bf16-split all four weights ----------------
// W stored [K][128] row-major -> W^T [n][K] hi/lo. 32x32 transpose tiles,
// n-tiles minor (4 per weight): tr=(tile>>2)*32 (k), tc=(tile&3)*32 (n).
__global__ void prep_w_kernel(const float* __restrict__ w0s, const float* __restrict__ w0n,
                              const float* __restrict__ w1s, const float* __restrict__ w1n) {
    __shared__ float t[32][33];
    int b = blockIdx.x;
    const float* W; int K, off, tile;
    if (b < 16)      { W = w0s; K = 128; off = 0;     tile = b; }
    else if (b < 32) { W = w0n; K = 128; off = 16384; tile = b - 16; }
    else if (b < 64) { W = w1s; K = 256; off = 32768; tile = b - 32; }
    else             { W = w1n; K = 256; off = 65536; tile = b - 64; }
    int tr = (tile >> 2) * 32;   // k base
    int tc = (tile & 3) * 32;    // n base
    int tx = threadIdx.x & 31, ty = threadIdx.x >> 5;   // 32x8
#pragma unroll
    for (int p = 0; p < 32; p += 8)
        t[ty + p][tx] = W[(size_t)(tr + ty + p) * 128 + tc + tx];
    __syncthreads();
#pragma unroll
    for (int p = 0; p < 32; p += 8) {
        int n = tc + ty + p, k = tr + tx;
        float v = t[tx][ty + p];
        __nv_bfloat16 h = __float2bfloat16(v);
        __nv_bfloat16 l = __float2bfloat16(v - __bfloat162float(h));
        size_t o = (size_t)off + (size_t)n * K + k;
        g_WtH[o] = h;
        g_WtL[o] = l;
    }
}

// ---------------- mega kernel: 32 gather0 blocks + 800 fused gather/GEMM blocks ----------------
#define PADB 272   // smem row pitch in bytes
#define G0_BLOCKS 32

__global__ __launch_bounds__(256, 2)
void mega_kernel(const float* __restrict__ feat,
                 const int* __restrict__ s0,
                 const int* __restrict__ s1,
                 const int* __restrict__ s2) {
    const int tid = threadIdx.x;
    const int wid = tid >> 5;
    const int lane = tid & 31;
    const int c = lane * 4;

    if (blockIdx.x < G0_BLOCKS) {
        int wg = blockIdx.x * 8 + wid;    // 0..255
#pragma unroll
        for (int i = 0; i < 4; i++) {
            int row = wg * 4 + i;
            long iself = s0[row];
            *(float4*)(g_X0 + (size_t)row * 256 + c) =
                *(const float4*)(feat + iself * DF + c);

            const int* p = s1 + (size_t)row * NS1;
            int idxs[NS1];
#pragma unroll
            for (int j = 0; j < NS1; j++) idxs[j] = p[j];
            float4 acc = make_float4(0.f, 0.f, 0.f, 0.f);
#pragma unroll
            for (int base = 0; base < 25; base += 5) {
                float4 v[5];
#pragma unroll
                for (int j = 0; j < 5; j++)
                    v[j] = *(const float4*)(feat + (long)idxs[base + j] * DF + c);
                f4add(v[0], v[1]); f4add(v[2], v[3]); f4add(v[0], v[2]);
                f4add(v[0], v[4]); f4add(acc, v[0]);
            }
            const float s = 1.0f / NS1;
            acc.x *= s; acc.y *= s; acc.z *= s; acc.w *= s;
            *(float4*)(g_X0 + (size_t)row * 256 + 128 + c) = acc;
        }
        return;
    }

    extern __shared__ char sb[];
    const uint32_t OFF_AH = 0;
    const uint32_t OFF_AL = 64 * PADB;
    const uint32_t OFF_BH = 2 * 64 * PADB;
    const uint32_t OFF_BL = OFF_BH + 128 * PADB;
    const uint32_t smb = smem_to_u32(sb);

    const int bid2 = blockIdx.x - G0_BLOCKS;
    const int half = bid2 & 1;
    const int row0 = (bid2 >> 1) * 64;

    for (int idx = tid; idx < 2048; idx += 256) {
        int n = idx >> 4;
        int ch = (idx & 15) * 16;
        size_t gsrc = (size_t)half * 16384 + (size_t)n * 128;
        uint32_t dst = n * PADB + ch;
        CP_ASYNC16(smb + OFF_BH + dst, (const char*)(g_WtH + gsrc) + ch);
        CP_ASYNC16(smb + OFF_BL + dst, (const char*)(g_WtL + gsrc) + ch);
    }

    if (half == 0) {
        long idxs[8];
#pragma unroll
        for (int it = 0; it < 8; it++) idxs[it] = s1[row0 + wid + it * 8];
        float4 v[8];
#pragma unroll
        for (int it = 0; it < 8; it++)
            v[it] = *(const float4*)(feat + idxs[it] * DF + c);
#pragma unroll
        for (int it = 0; it < 8; it++) {
            const int r = wid + it * 8;
            uint2 h, l;
            split4(v[it], h, l);
            *(uint2*)(sb + OFF_AH + r * PADB + lane * 8) = h;
            *(uint2*)(sb + OFF_AL + r * PADB + lane * 8) = l;
        }
    } else {
#pragma unroll
        for (int it = 0; it < 8; it++) {
            const int r = wid + it * 8;
            const int gr = row0 + r;
            const int* p = s2 + (size_t)gr * NS2;
            int idxs[NS2];
#pragma unroll
            for (int j = 0; j < NS2; j++) idxs[j] = p[j];
            float4 v[NS2];
#pragma unroll
            for (int j = 0; j < NS2; j++)
                v[j] = *(const float4*)(feat + (long)idxs[j] * DF + c);
            f4add(v[0], v[1]); f4add(v[2], v[3]); f4add(v[4], v[5]);
            f4add(v[6], v[7]); f4add(v[8], v[9]);
            f4add(v[0], v[2]); f4add(v[4], v[6]);
            f4add(v[0], v[4]); f4add(v[0], v[8]);
            const float s = 1.0f / NS2;
            v[0].x *= s; v[0].y *= s; v[0].z *= s; v[0].w *= s;
            uint2 h, l;
            split4(v[0], h, l);
            *(uint2*)(sb + OFF_AH + r * PADB + lane * 8) = h;
            *(uint2*)(sb + OFF_AL + r * PADB + lane * 8) = l;
        }
    }
    CP_ASYNC_WAIT_ALL();
    __syncthreads();

    const char* Ah = sb + OFF_AH;
    const char* Al = sb + OFF_AL;
    const char* Bh = sb + OFF_BH;
    const char* Bl = sb + OFF_BL;

    const int g = lane >> 2;
    const int tg = lane & 3;
    const int wr = (wid >> 2) * 32;
    const int wc = (wid & 3) * 32;

    float acc[2][4][4];
#pragma unroll
    for (int i = 0; i < 2; i++)
#pragma unroll
        for (int j = 0; j < 4; j++)
#pragma unroll
            for (int q = 0; q < 4; q++) acc[i][j][q] = 0.f;

#pragma unroll
    for (int ks = 0; ks < 8; ks++) {
        const int kb = (ks * 16 + tg * 2) * 2;
        uint32_t ah[2][4], al[2][4], bh[4][2], bl[4][2];
#pragma unroll
        for (int i = 0; i < 2; i++) {
            int r = wr + i * 16 + g;
            ah[i][0] = *(const uint32_t*)(Ah + r * PADB + kb);
            ah[i][1] = *(const uint32_t*)(Ah + (r + 8) * PADB + kb);
            ah[i][2] = *(const uint32_t*)(Ah + r * PADB + kb + 16);
            ah[i][3] = *(const uint32_t*)(Ah + (r + 8) * PADB + kb + 16);
            al[i][0] = *(const uint32_t*)(Al + r * PADB + kb);
            al[i][1] = *(const uint32_t*)(Al + (r + 8) * PADB + kb);
            al[i][2] = *(const uint32_t*)(Al + r * PADB + kb + 16);
            al[i][3] = *(const uint32_t*)(Al + (r + 8) * PADB + kb + 16);
        }
#pragma unroll
        for (int j = 0; j < 4; j++) {
            int n = wc + j * 8 + g;
            bh[j][0] = *(const uint32_t*)(Bh + n * PADB + kb);
            bh[j][1] = *(const uint32_t*)(Bh + n * PADB + kb + 16);
            bl[j][0] = *(const uint32_t*)(Bl + n * PADB + kb);
            bl[j][1] = *(const uint32_t*)(Bl + n * PADB + kb + 16);
        }
#pragma unroll
        for (int i = 0; i < 2; i++)
#pragma unroll
            for (int j = 0; j < 4; j++) {
                mma16816(acc[i][j], ah[i], bh[j]);
                mma16816(acc[i][j], al[i], bh[j]);
                mma16816(acc[i][j], ah[i], bl[j]);
            }
    }

    const int colg = half * 128 + wc;
    const float inv25 = 1.0f / NS1;
#pragma unroll
    for (int i = 0; i < 2; i++) {
        int r0g = row0 + wr + i * 16 + g;
        int b0 = r0g / NS1;
        int b1 = (r0g + 8) / NS1;
#pragma unroll
        for (int j = 0; j < 4; j++) {
            int cgl = colg + j * 8 + tg * 2;
            atomicAdd(&g_M1[(size_t)b0 * 256 + cgl],     fmaxf(acc[i][j][0], 0.f) * inv25);
            atomicAdd(&g_M1[(size_t)b0 * 256 + cgl + 1], fmaxf(acc[i][j][1], 0.f) * inv25);
            atomicAdd(&g_M1[(size_t)b1 * 256 + cgl],     fmaxf(acc[i][j][2], 0.f) * inv25);
            atomicAdd(&g_M1[(size_t)b1 * 256 + cgl + 1], fmaxf(acc[i][j][3], 0.f) * inv25);
        }
    }
}

// ---------------- small HMMA GEMM: out[:, h*128+n] = relu(A_h @ W_h) ----------------
// grid (16, 2): 64-row tile x half. kc_count k-chunks of 128 accumulate in regs.
// A rows stride 256 fp32; window col = acolmul*half + kc*128.
__global__ __launch_bounds__(256, 2)
void small_hmma_kernel(const float* __restrict__ A0, const float* __restrict__ A1,
                       int acolmul, int woffbase, int woffstep, int kstride,
                       int kc_count, float* __restrict__ out) {
    extern __shared__ char sb[];
    const uint32_t OFF_AH = 0;
    const uint32_t OFF_AL = 64 * PADB;
    const uint32_t OFF_BH = 2 * 64 * PADB;
    const uint32_t OFF_BL = OFF_BH + 128 * PADB;
    const uint32_t smb = smem_to_u32(sb);

    const int half = blockIdx.y;
    const int row0 = blockIdx.x * 64;
    const int tid = threadIdx.x;
    const int wid = tid >> 5;
    const int lane = tid & 31;
    const float* A = half ? A1 : A0;
    const int acol0 = acolmul * half;
    const int woff = woffbase + half * woffstep;

    const int g = lane >> 2;
    const int tg = lane & 3;
    const int wr = (wid >> 2) * 32;
    const int wc = (wid & 3) * 32;

    float acc[2][4][4];
#pragma unroll
    for (int i = 0; i < 2; i++)
#pragma unroll
        for (int j = 0; j < 4; j++)
#pragma unroll
            for (int q = 0; q < 4; q++) acc[i][j][q] = 0.f;

    for (int kc = 0; kc < kc_count; kc++) {
        const int koff = kc * 128;
        // stage B chunk via cp.async
        for (int idx = tid; idx < 2048; idx += 256) {
            int n = idx >> 4;
            int ch = (idx & 15) * 16;
            size_t gsrc = (size_t)woff + (size_t)n * kstride + koff;
            uint32_t dst = n * PADB + ch;
            CP_ASYNC16(smb + OFF_BH + dst, (const char*)(g_WtH + gsrc) + ch);
            CP_ASYNC16(smb + OFF_BL + dst, (const char*)(g_WtL + gsrc) + ch);
        }
        // stage A chunk: 64 rows x 128 fp32 -> bf16 hi/lo
        for (int idx = tid; idx < 2048; idx += 256) {
            int r = idx >> 5;
            int cc4 = (idx & 31) * 4;
            float4 v = *(const float4*)(A + (size_t)(row0 + r) * 256 + acol0 + koff + cc4);
            uint2 h, l;
            split4(v, h, l);
            *(uint2*)(sb + OFF_AH + r * PADB + cc4 * 2) = h;
            *(uint2*)(sb + OFF_AL + r * PADB + cc4 * 2) = l;
        }
        CP_ASYNC_WAIT_ALL();
        __syncthreads();

        const char* Ah = sb + OFF_AH;
        const char* Al = sb + OFF_AL;
        const char* Bh = sb + OFF_BH;
        const char* Bl = sb + OFF_BL;

#pragma unroll
        for (int ks = 0; ks < 8; ks++) {
            const int kb = (ks * 16 + tg * 2) * 2;
            uint32_t ah[2][4], al[2][4], bh[4][2], bl[4][2];
#pragma unroll
            for (int i = 0; i < 2; i++) {
                int r = wr + i * 16 + g;
                ah[i][0] = *(const uint32_t*)(Ah + r * PADB + kb);
                ah[i][1] = *(const uint32_t*)(Ah + (r + 8) * PADB + kb);
                ah[i][2] = *(const uint32_t*)(Ah + r * PADB + kb + 16);
                ah[i][3] = *(const uint32_t*)(Ah + (r + 8) * PADB + kb + 16);
                al[i][0] = *(const uint32_t*)(Al + r * PADB + kb);
                al[i][1] = *(const uint32_t*)(Al + (r + 8) * PADB + kb);
                al[i][2] = *(const uint32_t*)(Al + r * PADB + kb + 16);
                al[i][3] = *(const uint32_t*)(Al + (r + 8) * PADB + kb + 16);
            }
#pragma unroll
            for (int j = 0; j < 4; j++) {
                int n = wc + j * 8 + g;
                bh[j][0] = *(const uint32_t*)(Bh + n * PADB + kb);
                bh[j][1] = *(const uint32_t*)(Bh + n * PADB + kb + 16);
                bl[j][0] = *(const uint32_t*)(Bl + n * PADB + kb);
                bl[j][1] = *(const uint32_t*)(Bl + n * PADB + kb + 16);
            }
#pragma unroll
            for (int i = 0; i < 2; i++)
#pragma unroll
                for (int j = 0; j < 4; j++) {
                    mma16816(acc[i][j], ah[i], bh[j]);
                    mma16816(acc[i][j], al[i], bh[j]);
                    mma16816(acc[i][j], ah[i], bl[j]);
                }
        }
        __syncthreads();
    }

    // epilogue: relu + STG
    const int colg = half * 128 + wc;
#pragma unroll
    for (int i = 0; i < 2; i++) {
        int r = row0 + wr + i * 16 + g;
#pragma unroll
        for (int j = 0; j < 4; j++) {
            int cgl = colg + j * 8 + tg * 2;
            float2 o0, o1;
            o0.x = fmaxf(acc[i][j][0], 0.f);
            o0.y = fmaxf(acc[i][j][1], 0.f);
            o1.x = fmaxf(acc[i][j][2], 0.f);
            o1.y = fmaxf(acc[i][j][3], 0.f);
            *(float2*)(out + (size_t)r * 256 + cgl) = o0;
            *(float2*)(out + (size_t)(r + 8) * 256 + cgl) = o1;
        }
    }
}

// ---------------- launch ----------------
extern "C" void kernel_launch(void* const* d_in, const int* in_sizes, int n_in,
                              void* d_out, int out_size) {
    const float* feat = (const float*)d_in[0];
    const float* ws0  = (const float*)d_in[1];
    const float* wn0  = (const float*)d_in[2];
    const float* ws1  = (const float*)d_in[3];
    const float* wn1  = (const float*)d_in[4];
    const int*   s0   = (const int*)d_in[5];
    const int*   s1   = (const int*)d_in[6];
    const int*   s2   = (const int*)d_in[7];
    float* out = (float*)d_out;

    float *pX0, *pY0, *pM1;
    cudaGetSymbolAddress((void**)&pX0, g_X0);
    cudaGetSymbolAddress((void**)&pY0, g_Y0);
    cudaGetSymbolAddress((void**)&pM1, g_M1);

    const size_t smMMA = (size_t)(2 * 64 + 2 * 128) * PADB;   // 104448
    cudaFuncSetAttribute(mega_kernel,
                         cudaFuncAttributeMaxDynamicSharedMemorySize, (int)smMMA);
    cudaFuncSetAttribute(small_hmma_kernel,
                         cudaFuncAttributeMaxDynamicSharedMemorySize, (int)smMMA);

    // 1) prep all four weights -> transposed bf16 hi/lo
    prep_w_kernel<<<96, 256>>>(ws0, wn0, ws1, wn1);
    // 2) zero M1 accumulator
    zero_m1_kernel<<<256, 256>>>();
    // 3) mega: gather0 (32 blocks) + fused gather/GEMM/atomic-mean (800 blocks)
    mega_kernel<<<G0_BLOCKS + 2 * (ROWS1 / 64), 256, smMMA>>>(feat, s0, s1, s2);
    // 4) Y0 = relu([X0s@Ws0 | X0n@Wn0])   (HMMA, K=128, 1 chunk)
    small_hmma_kernel<<<dim3(16, 2), 256, smMMA>>>(pX0, pX0, 128, 0, 16384, 128, 1, pY0);
    // 5) out = relu([Y0@Ws1 | M1@Wn1])    (HMMA, K=256, 2 chunks)
    small_hmma_kernel<<<dim3(16, 2), 256, smMMA>>>(pY0, pM1, 0, 32768, 32768, 256, 2, out);
}